// round 14
// baseline (speedup 1.0000x reference)
#include <cuda_runtime.h>
#include <cuda_fp16.h>
#include <cstdint>

#define NN 100000
#define NE 800000
#define NG 512
#define D  128
#define EPSV 1e-5f
#define NT2 391              // ceil(NN/256)
#define SCAN_B 391           // ceil(NN/256)
#define NSLOT 32
#define AGG_GRID 1184        // 148 SMs x 8 CTAs (one full wave @ 256 thr)

// ---------------- scratch (static device globals; no allocations) ----------------
__device__ __half g_bufA[NN * D];
__device__ __half g_bufB[NN * D];
__device__ float  g_dinv[NN];
__device__ float  g_selfw[NN];
__device__ int    g_cnt[NN];         // zero at load; re-zeroed by k_fill each call
__device__ int    g_fill[NN];
__device__ int    g_off[NN + 1];
__device__ int2   g_edge[NE];        // (src, __float_as_int(w))
__device__ int    g_part[SCAN_B];
__device__ int    g_pbase[SCAN_B];
__device__ int    g_ticket[4];       // per-layer work-stealing cursors
__device__ float  g_psum3[3 * NSLOT * D];   // per-layer BN partial sums
__device__ float  g_psq3[3 * NSLOT * D];
__device__ int    g_start[NG];
__device__ int    g_end[NG];
__device__ __half g_Wh16[3 * D * D];   // W^T per layer, [n][k], fp16

__device__ __forceinline__ int clampN(int v) {
    return v < 0 ? 0 : (v >= NN ? NN - 1 : v);
}

__device__ __forceinline__ uint32_t smem_u32(const void* p) {
    uint32_t a;
    asm("{ .reg .u64 t; cvta.to.shared.u64 t, %1; cvt.u32.u64 %0, t; }" : "=r"(a) : "l"(p));
    return a;
}

// XOR swizzle for 256B rows
__device__ __forceinline__ uint32_t sw(uint32_t off) {
    return off ^ ((off >> 4) & 0x70);
}

__device__ __forceinline__ void ldm_x4(uint32_t* r, uint32_t addr) {
    asm volatile("ldmatrix.sync.aligned.m8n8.x4.shared.b16 {%0,%1,%2,%3}, [%4];"
                 : "=r"(r[0]), "=r"(r[1]), "=r"(r[2]), "=r"(r[3]) : "r"(addr));
}

__device__ __forceinline__ void mma_f16(float* c, const uint32_t* a, uint32_t b0, uint32_t b1) {
    asm volatile(
        "mma.sync.aligned.m16n8k16.row.col.f32.f16.f16.f32 "
        "{%0,%1,%2,%3}, {%4,%5,%6,%7}, {%8,%9}, {%0,%1,%2,%3};"
        : "+f"(c[0]), "+f"(c[1]), "+f"(c[2]), "+f"(c[3])
        : "r"(a[0]), "r"(a[1]), "r"(a[2]), "r"(a[3]), "r"(b0), "r"(b1));
}

// typed pair loader -> fp32
__device__ __forceinline__ float2 load_pair_f(const float* base, int idx) {
    return __ldg((const float2*)base + idx);
}
__device__ __forceinline__ float2 load_pair_f(const __half* base, int idx) {
    return __half22float2(__ldg((const __half2*)base + idx));
}

// ---------------- graph preprocessing ----------------
__global__ void k_count(const int* __restrict__ ei) {
    int e = blockIdx.x * blockDim.x + threadIdx.x;
    if (e < NE) atomicAdd(&g_cnt[clampN(ei[NE + e])], 1);
}

// node-wise derived values + per-256-chunk partial sums (+ticket/psum reset)
__global__ void k_nodepart() {
    __shared__ int s[256];
    int t = threadIdx.x;
    int i = blockIdx.x * 256 + t;
    int c = (i < NN) ? g_cnt[i] : 0;
    if (i < NN) {
        float deg = (float)c + 1.0f;
        g_dinv[i]  = rsqrtf(deg);
        g_selfw[i] = 1.0f / deg;
        g_fill[i]  = 0;
    }
    if (i < NG) { g_start[i] = 0; g_end[i] = 0; }
    if (i < 3 * NSLOT * D) { g_psum3[i] = 0.f; g_psq3[i] = 0.f; }
    if (i < 4) g_ticket[i] = 0;
    s[t] = c;
    __syncthreads();
    for (int o = 128; o; o >>= 1) { if (t < o) s[t] += s[t + o]; __syncthreads(); }
    if (t == 0) g_part[blockIdx.x] = s[0];
}

__global__ void k_scanpart() {
    __shared__ int s[512];
    int t = threadIdx.x;
    int v = (t < SCAN_B) ? g_part[t] : 0;
    s[t] = v; __syncthreads();
    for (int d = 1; d < 512; d <<= 1) {
        int x = (t >= d) ? s[t - d] : 0;
        __syncthreads();
        s[t] += x;
        __syncthreads();
    }
    if (t < SCAN_B) g_pbase[t] = s[t] - v;
    if (t == SCAN_B - 1) g_off[NN] = s[t];
}

__global__ void k_offsets() {
    __shared__ int s[256];
    int t = threadIdx.x;
    int i = blockIdx.x * 256 + t;
    int v = (i < NN) ? g_cnt[i] : 0;
    s[t] = v; __syncthreads();
    for (int d = 1; d < 256; d <<= 1) {
        int x = (t >= d) ? s[t - d] : 0;
        __syncthreads();
        s[t] += x;
        __syncthreads();
    }
    if (i < NN) g_off[i] = g_pbase[blockIdx.x] + s[t] - v;
}

// fill CSR + compute segment bounds (merged k_fill + k_bounds) + cnt reset
__global__ void k_fillbounds(const int* __restrict__ ei, const int* __restrict__ batch) {
    int e = blockIdx.x * blockDim.x + threadIdx.x;
    if (e < NN) {
        g_cnt[e] = 0;          // reset for the NEXT call
        int b = batch[e];
        if (b < 0) b = 0; if (b >= NG) b = NG - 1;
        int bp = (e == 0) ? -1 : batch[e - 1];
        int bn = (e == NN - 1) ? -1 : batch[e + 1];
        if (e == 0      || bp != b) g_start[b] = e;
        if (e == NN - 1 || bn != b) g_end[b]   = e + 1;
    }
    if (e >= NE) return;
    int s = clampN(ei[e]);
    int d = clampN(ei[NE + e]);
    int p = g_off[d] + atomicAdd(&g_fill[d], 1);
    g_edge[p] = make_int2(s, __float_as_int(g_dinv[s] * g_dinv[d]));
}

// W^T fp16
__global__ void k_prepw(const float* __restrict__ Ws) {
    int idx = blockIdx.x * 128 + threadIdx.x;
    int l = idx >> 14, rem = idx & 16383;
    int n = rem >> 7, k = rem & 127;
    g_Wh16[idx] = __float2half_rn(Ws[l * 16384 + k * 128 + n]);
}

// compute BN affine for layer l from slotted partials (thread f < 128)
__device__ __forceinline__ void bn_affine(int layer, int f,
                                          const float* __restrict__ gamma,
                                          const float* __restrict__ beta,
                                          float& sc_out, float& sh_out) {
    const float* ps = g_psum3 + layer * NSLOT * D;
    const float* pq = g_psq3  + layer * NSLOT * D;
    float s = 0.f, q = 0.f;
#pragma unroll
    for (int k = 0; k < NSLOT; k++) {
        s += ps[k * D + f];
        q += pq[k * D + f];
    }
    float mu  = s / (float)NN;
    float var = q / (float)NN - mu * mu;
    float rstd = rsqrtf(var + EPSV);
    float sc = rstd * gamma[f];
    sc_out = sc;
    sh_out = beta[f] - mu * sc;
}

// ---------------- fp16 HMMA GEMM (in-kernel BN affine; 3 CTAs/SM target) ----------------
#define S_SC 32768
#define S_SH (32768 + 512)
#define MMASMEM (32768 + 1024)

template <typename T>
__global__ __launch_bounds__(256, 3) void k_gemm16(const T* __restrict__ in,
                                                   const __half* __restrict__ Wh,
                                                   __half* __restrict__ out,
                                                   int apply, int prev_layer,
                                                   const float* __restrict__ gamma,
                                                   const float* __restrict__ beta) {
    extern __shared__ char smc[];
    uint32_t sb = smem_u32(smc);
    float* smsc = (float*)(smc + S_SC);
    float* smsh = (float*)(smc + S_SH);
    int tid = threadIdx.x, wid = tid >> 5, lane = tid & 31;
    int row0 = blockIdx.x * 256;

    if (apply && tid < D) {
        float sc, sh;
        bn_affine(prev_layer, tid, gamma, beta, sc, sh);
        smsc[tid] = sc;
        smsh[tid] = sh;
    }

    // ---- stage W^T
    {
        int n = tid >> 1, hf = tid & 1;
        const uint4* src_h = (const uint4*)(Wh) + n * 16 + hf * 8;
        uint32_t base = n * 256 + hf * 128;
#pragma unroll
        for (int c = 0; c < 8; c++) {
            uint32_t o = sw(base + c * 16);
            *(uint4*)(smc + o) = __ldg(&src_h[c]);
        }
    }
    __syncthreads();

    // ---- A fragments: 2 sets of 16 rows, direct global loads (+BN/ReLU)
    int groupID = lane >> 2, tig = lane & 3;
    int rb = row0 + wid * 32;
    uint32_t af[2][8][4];
    bool okr[2][2];
#pragma unroll
    for (int s = 0; s < 2; s++) {
        int r0 = rb + s * 16 + groupID;
        int r1 = r0 + 8;
        okr[s][0] = r0 < NN; okr[s][1] = r1 < NN;
        const T* bp0 = in + (size_t)r0 * D;
        const T* bp1 = in + (size_t)r1 * D;
#pragma unroll
        for (int k = 0; k < 8; k++) {
            float2 f0 = okr[s][0] ? load_pair_f(bp0, tig + k * 8)     : make_float2(0.f, 0.f);
            float2 f1 = okr[s][1] ? load_pair_f(bp1, tig + k * 8)     : make_float2(0.f, 0.f);
            float2 f2 = okr[s][0] ? load_pair_f(bp0, tig + k * 8 + 4) : make_float2(0.f, 0.f);
            float2 f3 = okr[s][1] ? load_pair_f(bp1, tig + k * 8 + 4) : make_float2(0.f, 0.f);
            if (apply) {
                float2 s0 = ((const float2*)smsc)[tig + k * 8];
                float2 h0 = ((const float2*)smsh)[tig + k * 8];
                float2 s1 = ((const float2*)smsc)[tig + k * 8 + 4];
                float2 h1 = ((const float2*)smsh)[tig + k * 8 + 4];
                f0.x = fmaxf(fmaf(f0.x, s0.x, h0.x), 0.f);
                f0.y = fmaxf(fmaf(f0.y, s0.y, h0.y), 0.f);
                f1.x = fmaxf(fmaf(f1.x, s0.x, h0.x), 0.f);
                f1.y = fmaxf(fmaf(f1.y, s0.y, h0.y), 0.f);
                f2.x = fmaxf(fmaf(f2.x, s1.x, h1.x), 0.f);
                f2.y = fmaxf(fmaf(f2.y, s1.y, h1.y), 0.f);
                f3.x = fmaxf(fmaf(f3.x, s1.x, h1.x), 0.f);
                f3.y = fmaxf(fmaf(f3.y, s1.y, h1.y), 0.f);
            }
            __half2 a0 = __floats2half2_rn(f0.x, f0.y);
            __half2 a1 = __floats2half2_rn(f1.x, f1.y);
            __half2 a2 = __floats2half2_rn(f2.x, f2.y);
            __half2 a3 = __floats2half2_rn(f3.x, f3.y);
            af[s][k][0] = *(uint32_t*)&a0;
            af[s][k][1] = *(uint32_t*)&a1;
            af[s][k][2] = *(uint32_t*)&a2;
            af[s][k][3] = *(uint32_t*)&a3;
        }
    }

    uint32_t b_base = ((lane & 7) + ((lane >> 4) << 3)) * 256 + (((lane >> 3) & 1) * 8) * 2;
    int col_t = tig * 2;

#pragma unroll 2
    for (int np = 0; np < 8; np++) {
        float e0[4] = {0,0,0,0}, o0[4] = {0,0,0,0};
        float e1[4] = {0,0,0,0}, o1[4] = {0,0,0,0};
#pragma unroll
        for (int k = 0; k < 8; k++) {
            uint32_t bh[4];
            uint32_t o = sw(b_base + np * 4096 + k * 32);
            ldm_x4(bh, sb + o);
            mma_f16(e0, af[0][k], bh[0], bh[1]);
            mma_f16(o0, af[0][k], bh[2], bh[3]);
            mma_f16(e1, af[1][k], bh[0], bh[1]);
            mma_f16(o1, af[1][k], bh[2], bh[3]);
        }
        int nb = np * 16;
#pragma unroll
        for (int s = 0; s < 2; s++) {
            float* ee = s ? e1 : e0; float* oo = s ? o1 : o0;
            int r0 = rb + s * 16 + groupID;
            int r1 = r0 + 8;
            if (okr[s][0]) {
                *(__half2*)(out + (size_t)r0 * D + nb + col_t)     = __floats2half2_rn(ee[0], ee[1]);
                *(__half2*)(out + (size_t)r0 * D + nb + 8 + col_t) = __floats2half2_rn(oo[0], oo[1]);
            }
            if (okr[s][1]) {
                *(__half2*)(out + (size_t)r1 * D + nb + col_t)     = __floats2half2_rn(ee[2], ee[3]);
                *(__half2*)(out + (size_t)r1 * D + nb + 8 + col_t) = __floats2half2_rn(oo[2], oo[3]);
            }
        }
    }
}

// ---------------- aggregation (gather, CSR, work-stealing) + bias + BN stats ----------------
__device__ __forceinline__ float4 h4_to_f4(uint2 raw) {
    __half2 a = *(__half2*)&raw.x;
    __half2 b = *(__half2*)&raw.y;
    float2 fa = __half22float2(a), fb = __half22float2(b);
    return make_float4(fa.x, fa.y, fb.x, fb.y);
}

__device__ __forceinline__ void acc4(float4& acc, float w, float4 v) {
    acc.x = fmaf(w, v.x, acc.x);
    acc.y = fmaf(w, v.y, acc.y);
    acc.z = fmaf(w, v.z, acc.z);
    acc.w = fmaf(w, v.w, acc.w);
}

__global__ __launch_bounds__(256) void k_agg(const __half* __restrict__ tmp,
                                             __half* __restrict__ outh,
                                             const float* __restrict__ bias,
                                             int layer) {
    __shared__ float bsum[D];
    __shared__ float bsq[D];
    int tid = threadIdx.x;
    if (tid < D) { bsum[tid] = 0.f; bsq[tid] = 0.f; }
    __syncthreads();

    int lane = tid & 31;
    const uint2* t2 = (const uint2*)tmp;
    float4 b4 = ((const float4*)bias)[lane];
    float ls0 = 0, ls1 = 0, ls2 = 0, ls3 = 0;
    float lq0 = 0, lq1 = 0, lq2 = 0, lq3 = 0;

    for (;;) {
        int base;
        if (lane == 0) base = atomicAdd(&g_ticket[layer], 4);
        base = __shfl_sync(0xffffffffu, base, 0);
        if (base >= NN) break;
        int rend = base + 4 < NN ? base + 4 : NN;
        for (int row = base; row < rend; row++) {
            float4 acc = make_float4(0.f, 0.f, 0.f, 0.f);
            int e0 = g_off[row], e1 = g_off[row + 1];
            int e = e0;
            for (; e + 4 <= e1; e += 4) {
                int2 p0 = __ldg(&g_edge[e]);
                int2 p1 = __ldg(&g_edge[e + 1]);
                int2 p2 = __ldg(&g_edge[e + 2]);
                int2 p3 = __ldg(&g_edge[e + 3]);
                float4 v0 = h4_to_f4(__ldg(&t2[p0.x * 32 + lane]));
                float4 v1 = h4_to_f4(__ldg(&t2[p1.x * 32 + lane]));
                float4 v2 = h4_to_f4(__ldg(&t2[p2.x * 32 + lane]));
                float4 v3 = h4_to_f4(__ldg(&t2[p3.x * 32 + lane]));
                acc4(acc, __int_as_float(p0.y), v0);
                acc4(acc, __int_as_float(p1.y), v1);
                acc4(acc, __int_as_float(p2.y), v2);
                acc4(acc, __int_as_float(p3.y), v3);
            }
            for (; e < e1; e++) {
                int2 pp = __ldg(&g_edge[e]);
                float4 v = h4_to_f4(__ldg(&t2[pp.x * 32 + lane]));
                acc4(acc, __int_as_float(pp.y), v);
            }
            float sw_ = g_selfw[row];
            float4 v = h4_to_f4(__ldg(&t2[row * 32 + lane]));
            acc.x = fmaf(sw_, v.x, acc.x) + b4.x;
            acc.y = fmaf(sw_, v.y, acc.y) + b4.y;
            acc.z = fmaf(sw_, v.z, acc.z) + b4.z;
            acc.w = fmaf(sw_, v.w, acc.w) + b4.w;
            uint2 packed;
            *(__half2*)&packed.x = __floats2half2_rn(acc.x, acc.y);
            *(__half2*)&packed.y = __floats2half2_rn(acc.z, acc.w);
            ((uint2*)outh)[row * 32 + lane] = packed;
            ls0 += acc.x; ls1 += acc.y; ls2 += acc.z; ls3 += acc.w;
            lq0 += acc.x * acc.x; lq1 += acc.y * acc.y;
            lq2 += acc.z * acc.z; lq3 += acc.w * acc.w;
        }
    }

    atomicAdd(&bsum[lane * 4 + 0], ls0); atomicAdd(&bsum[lane * 4 + 1], ls1);
    atomicAdd(&bsum[lane * 4 + 2], ls2); atomicAdd(&bsum[lane * 4 + 3], ls3);
    atomicAdd(&bsq[lane * 4 + 0], lq0);  atomicAdd(&bsq[lane * 4 + 1], lq1);
    atomicAdd(&bsq[lane * 4 + 2], lq2);  atomicAdd(&bsq[lane * 4 + 3], lq3);
    __syncthreads();
    if (tid < D) {
        int slot = (layer * NSLOT + (blockIdx.x & (NSLOT - 1))) * D + tid;
        atomicAdd(&g_psum3[slot], bsum[tid]);
        atomicAdd(&g_psq3[slot],  bsq[tid]);
    }
}

// ---------------- fused pool (BN affine layer 2) + MLP head ----------------
__global__ __launch_bounds__(256) void k_poolhead(const __half* __restrict__ h,
                                                  const float* __restrict__ gamma,
                                                  const float* __restrict__ beta,
                                                  const float* __restrict__ W1,
                                                  const float* __restrict__ b1,
                                                  const float* __restrict__ W2,
                                                  const float* __restrict__ b2,
                                                  float* __restrict__ out) {
    __shared__ float zs[D];
    __shared__ float partial[D];
    __shared__ float smsc[D];
    __shared__ float smsh[D];
    __shared__ float red[4];
    int g = blockIdx.x, t = threadIdx.x;
    int f = t & 127, hf = t >> 7;
    if (t < D) {
        float sc, sh;
        bn_affine(2, t, gamma, beta, sc, sh);
        smsc[t] = sc;
        smsh[t] = sh;
    }
    __syncthreads();
    int a = g_start[g], b = g_end[g];
    int n = b - a;
    int mid = a + (n >> 1);
    int lo = hf ? mid : a;
    int hi = hf ? b : mid;
    float sc = smsc[f], sh = smsh[f];
    float s0 = 0.f, s1 = 0.f;
    int i = lo;
    for (; i + 2 <= hi; i += 2) {
        s0 += fmaxf(fmaf(__half2float(h[(i + 0) * D + f]), sc, sh), 0.f);
        s1 += fmaxf(fmaf(__half2float(h[(i + 1) * D + f]), sc, sh), 0.f);
    }
    for (; i < hi; i++) s0 += fmaxf(fmaf(__half2float(h[i * D + f]), sc, sh), 0.f);
    float s = s0 + s1;
    if (hf) partial[f] = s;
    __syncthreads();
    if (!hf) zs[f] = (s + partial[f]) / (float)(n > 0 ? n : 1);
    __syncthreads();

    // head: threads 0..127 compute hidden unit f, then warp-reduce dot with W2
    if (t < D) {
        float acc = b1[t];
#pragma unroll 8
        for (int k = 0; k < D; k++) acc = fmaf(zs[k], W1[k * D + t], acc);
        float hz = fmaxf(acc, 0.f);
        float p = hz * W2[t];
#pragma unroll
        for (int o = 16; o; o >>= 1) p += __shfl_down_sync(0xffffffffu, p, o);
        if ((t & 31) == 0) red[t >> 5] = p;
    }
    __syncthreads();
    if (t == 0) out[g] = red[0] + red[1] + red[2] + red[3] + b2[0];
}

// ---------------- launch ----------------
extern "C" void kernel_launch(void* const* d_in, const int* in_sizes, int n_in,
                              void* d_out, int out_size) {
    const float* x      = (const float*)d_in[0];
    const int*   ei     = (const int*)d_in[1];
    const int*   batch  = (const int*)d_in[2];
    const float* Ws     = (const float*)d_in[3];
    const float* bs     = (const float*)d_in[4];
    const float* gammas = (const float*)d_in[5];
    const float* betas  = (const float*)d_in[6];
    const float* W1     = (const float*)d_in[7];
    const float* b1     = (const float*)d_in[8];
    const float* W2     = (const float*)d_in[9];
    const float* b2     = (const float*)d_in[10];
    float* out = (float*)d_out;

    __half *A, *B, *wh;
    cudaGetSymbolAddress((void**)&A, g_bufA);
    cudaGetSymbolAddress((void**)&B, g_bufB);
    cudaGetSymbolAddress((void**)&wh, g_Wh16);
    cudaFuncSetAttribute(k_gemm16<float>,  cudaFuncAttributeMaxDynamicSharedMemorySize, MMASMEM);
    cudaFuncSetAttribute(k_gemm16<__half>, cudaFuncAttributeMaxDynamicSharedMemorySize, MMASMEM);

    static cudaStream_t s2 = [] {
        cudaStream_t s; cudaStreamCreateWithFlags(&s, cudaStreamNonBlocking); return s;
    }();
    static cudaEvent_t evFork = [] {
        cudaEvent_t e; cudaEventCreateWithFlags(&e, cudaEventDisableTiming); return e;
    }();
    static cudaEvent_t evJoin = [] {
        cudaEvent_t e; cudaEventCreateWithFlags(&e, cudaEventDisableTiming); return e;
    }();

    const int NB_E = (NE + 255) / 256;   // 3125

    cudaEventRecord(evFork, 0);
    cudaStreamWaitEvent(s2, evFork, 0);

    k_count<<<NB_E, 256, 0, s2>>>(ei);                                     // 0
    k_prepw<<<3 * D * D / 128, 128>>>(Ws);                                 // 1
    k_nodepart<<<SCAN_B, 256, 0, s2>>>();                                  // 2
    k_gemm16<float><<<NT2, 256, MMASMEM>>>(x, wh, B, 0, 0,
                                           gammas, betas);                 // 3 <- profiled
    k_scanpart<<<1, 512, 0, s2>>>();                                       // 4
    k_offsets<<<SCAN_B, 256, 0, s2>>>();                                   // 5
    k_fillbounds<<<NB_E, 256, 0, s2>>>(ei, batch);                         // 6

    cudaEventRecord(evJoin, s2);
    cudaStreamWaitEvent(0, evJoin, 0);

    for (int l = 0; l < 3; l++) {
        if (l > 0)
            k_gemm16<__half><<<NT2, 256, MMASMEM>>>(A, wh + l * D * D, B, 1, l - 1,
                                                    gammas + (l - 1) * D,
                                                    betas + (l - 1) * D);
        k_agg<<<AGG_GRID, 256>>>(B, A, bs + l * D, l);
    }

    k_poolhead<<<NG, 256>>>(A, gammas + 2 * D, betas + 2 * D, W1, b1, W2, b2, out);
}

// round 15
// speedup vs baseline: 1.0559x; 1.0559x over previous
#include <cuda_runtime.h>
#include <cuda_fp16.h>
#include <cstdint>

#define NN 100000
#define NE 800000
#define NG 512
#define D  128
#define EPSV 1e-5f
#define NT2 391              // ceil(NN/256)
#define SCAN_B 391           // ceil(NN/256)
#define NSLOT 32
#define AGG_GRID 1184        // 148 SMs x 8 CTAs (one full wave @ 256 thr)

// ---------------- scratch (static device globals; no allocations) ----------------
__device__ __half g_bufA[NN * D];
__device__ __half g_bufB[NN * D];
__device__ float  g_dinv[NN];
__device__ float  g_selfw[NN];
__device__ int    g_cnt[NN];         // zero at load; re-zeroed by k_fillbounds each call
__device__ int    g_fill[NN];
__device__ int    g_off[NN + 1];
__device__ int2   g_edge[NE];        // (src, __float_as_int(w))
__device__ int    g_part[SCAN_B];
__device__ int    g_pbase[SCAN_B];
__device__ int    g_ticket[4];       // per-layer work-stealing cursors
__device__ float  g_psum3[3 * NSLOT * D];   // per-layer BN partial sums
__device__ float  g_psq3[3 * NSLOT * D];
__device__ int    g_start[NG];
__device__ int    g_end[NG];
__device__ __half g_Wh16[3 * D * D];   // W^T per layer, [n][k], fp16

__device__ __forceinline__ int clampN(int v) {
    return v < 0 ? 0 : (v >= NN ? NN - 1 : v);
}

__device__ __forceinline__ uint32_t smem_u32(const void* p) {
    uint32_t a;
    asm("{ .reg .u64 t; cvta.to.shared.u64 t, %1; cvt.u32.u64 %0, t; }" : "=r"(a) : "l"(p));
    return a;
}

// XOR swizzle for 256B rows
__device__ __forceinline__ uint32_t sw(uint32_t off) {
    return off ^ ((off >> 4) & 0x70);
}

__device__ __forceinline__ void ldm_x4(uint32_t* r, uint32_t addr) {
    asm volatile("ldmatrix.sync.aligned.m8n8.x4.shared.b16 {%0,%1,%2,%3}, [%4];"
                 : "=r"(r[0]), "=r"(r[1]), "=r"(r[2]), "=r"(r[3]) : "r"(addr));
}

__device__ __forceinline__ void mma_f16(float* c, const uint32_t* a, uint32_t b0, uint32_t b1) {
    asm volatile(
        "mma.sync.aligned.m16n8k16.row.col.f32.f16.f16.f32 "
        "{%0,%1,%2,%3}, {%4,%5,%6,%7}, {%8,%9}, {%0,%1,%2,%3};"
        : "+f"(c[0]), "+f"(c[1]), "+f"(c[2]), "+f"(c[3])
        : "r"(a[0]), "r"(a[1]), "r"(a[2]), "r"(a[3]), "r"(b0), "r"(b1));
}

// typed pair loader -> fp32
__device__ __forceinline__ float2 load_pair_f(const float* base, int idx) {
    return __ldg((const float2*)base + idx);
}
__device__ __forceinline__ float2 load_pair_f(const __half* base, int idx) {
    return __half22float2(__ldg((const __half2*)base + idx));
}

// ---------------- graph preprocessing ----------------
__global__ void k_count(const int* __restrict__ ei) {
    int e = blockIdx.x * blockDim.x + threadIdx.x;
    if (e < NE) atomicAdd(&g_cnt[clampN(ei[NE + e])], 1);
}

// node-wise derived values + per-256-chunk partial sums (+ticket/psum reset)
__global__ void k_nodepart() {
    __shared__ int s[256];
    int t = threadIdx.x;
    int i = blockIdx.x * 256 + t;
    int c = (i < NN) ? g_cnt[i] : 0;
    if (i < NN) {
        float deg = (float)c + 1.0f;
        g_dinv[i]  = rsqrtf(deg);
        g_selfw[i] = 1.0f / deg;
        g_fill[i]  = 0;
    }
    if (i < NG) { g_start[i] = 0; g_end[i] = 0; }
    if (i < 3 * NSLOT * D) { g_psum3[i] = 0.f; g_psq3[i] = 0.f; }
    if (i < 4) g_ticket[i] = 0;
    s[t] = c;
    __syncthreads();
    for (int o = 128; o; o >>= 1) { if (t < o) s[t] += s[t + o]; __syncthreads(); }
    if (t == 0) g_part[blockIdx.x] = s[0];
}

__global__ void k_scanpart() {
    __shared__ int s[512];
    int t = threadIdx.x;
    int v = (t < SCAN_B) ? g_part[t] : 0;
    s[t] = v; __syncthreads();
    for (int d = 1; d < 512; d <<= 1) {
        int x = (t >= d) ? s[t - d] : 0;
        __syncthreads();
        s[t] += x;
        __syncthreads();
    }
    if (t < SCAN_B) g_pbase[t] = s[t] - v;
    if (t == SCAN_B - 1) g_off[NN] = s[t];
}

__global__ void k_offsets() {
    __shared__ int s[256];
    int t = threadIdx.x;
    int i = blockIdx.x * 256 + t;
    int v = (i < NN) ? g_cnt[i] : 0;
    s[t] = v; __syncthreads();
    for (int d = 1; d < 256; d <<= 1) {
        int x = (t >= d) ? s[t - d] : 0;
        __syncthreads();
        s[t] += x;
        __syncthreads();
    }
    if (i < NN) g_off[i] = g_pbase[blockIdx.x] + s[t] - v;
}

// fill CSR + compute segment bounds (merged) + cnt reset
__global__ void k_fillbounds(const int* __restrict__ ei, const int* __restrict__ batch) {
    int e = blockIdx.x * blockDim.x + threadIdx.x;
    if (e < NN) {
        g_cnt[e] = 0;          // reset for the NEXT call
        int b = batch[e];
        if (b < 0) b = 0; if (b >= NG) b = NG - 1;
        int bp = (e == 0) ? -1 : batch[e - 1];
        int bn = (e == NN - 1) ? -1 : batch[e + 1];
        if (e == 0      || bp != b) g_start[b] = e;
        if (e == NN - 1 || bn != b) g_end[b]   = e + 1;
    }
    if (e >= NE) return;
    int s = clampN(ei[e]);
    int d = clampN(ei[NE + e]);
    int p = g_off[d] + atomicAdd(&g_fill[d], 1);
    g_edge[p] = make_int2(s, __float_as_int(g_dinv[s] * g_dinv[d]));
}

// W^T fp16
__global__ void k_prepw(const float* __restrict__ Ws) {
    int idx = blockIdx.x * 128 + threadIdx.x;
    int l = idx >> 14, rem = idx & 16383;
    int n = rem >> 7, k = rem & 127;
    g_Wh16[idx] = __float2half_rn(Ws[l * 16384 + k * 128 + n]);
}

// compute BN affine for layer l from slotted partials (thread f < 128)
__device__ __forceinline__ void bn_affine(int layer, int f,
                                          const float* __restrict__ gamma,
                                          const float* __restrict__ beta,
                                          float& sc_out, float& sh_out) {
    const float* ps = g_psum3 + layer * NSLOT * D;
    const float* pq = g_psq3  + layer * NSLOT * D;
    float s = 0.f, q = 0.f;
#pragma unroll
    for (int k = 0; k < NSLOT; k++) {
        s += ps[k * D + f];
        q += pq[k * D + f];
    }
    float mu  = s / (float)NN;
    float var = q / (float)NN - mu * mu;
    float rstd = rsqrtf(var + EPSV);
    float sc = rstd * gamma[f];
    sc_out = sc;
    sh_out = beta[f] - mu * sc;
}

// ---------------- fp16 HMMA GEMM (in-kernel BN affine; natural regs, 2 CTAs/SM) ----------------
#define S_SC 32768
#define S_SH (32768 + 512)
#define MMASMEM (32768 + 1024)

template <typename T>
__global__ __launch_bounds__(256) void k_gemm16(const T* __restrict__ in,
                                                const __half* __restrict__ Wh,
                                                __half* __restrict__ out,
                                                int apply, int prev_layer,
                                                const float* __restrict__ gamma,
                                                const float* __restrict__ beta) {
    extern __shared__ char smc[];
    uint32_t sb = smem_u32(smc);
    float* smsc = (float*)(smc + S_SC);
    float* smsh = (float*)(smc + S_SH);
    int tid = threadIdx.x, wid = tid >> 5, lane = tid & 31;
    int row0 = blockIdx.x * 256;

    if (apply && tid < D) {
        float sc, sh;
        bn_affine(prev_layer, tid, gamma, beta, sc, sh);
        smsc[tid] = sc;
        smsh[tid] = sh;
    }

    // ---- stage W^T
    {
        int n = tid >> 1, hf = tid & 1;
        const uint4* src_h = (const uint4*)(Wh) + n * 16 + hf * 8;
        uint32_t base = n * 256 + hf * 128;
#pragma unroll
        for (int c = 0; c < 8; c++) {
            uint32_t o = sw(base + c * 16);
            *(uint4*)(smc + o) = __ldg(&src_h[c]);
        }
    }
    __syncthreads();

    // ---- A fragments: 2 sets of 16 rows, direct global loads (+BN/ReLU)
    int groupID = lane >> 2, tig = lane & 3;
    int rb = row0 + wid * 32;
    uint32_t af[2][8][4];
    bool okr[2][2];
#pragma unroll
    for (int s = 0; s < 2; s++) {
        int r0 = rb + s * 16 + groupID;
        int r1 = r0 + 8;
        okr[s][0] = r0 < NN; okr[s][1] = r1 < NN;
        const T* bp0 = in + (size_t)r0 * D;
        const T* bp1 = in + (size_t)r1 * D;
#pragma unroll
        for (int k = 0; k < 8; k++) {
            float2 f0 = okr[s][0] ? load_pair_f(bp0, tig + k * 8)     : make_float2(0.f, 0.f);
            float2 f1 = okr[s][1] ? load_pair_f(bp1, tig + k * 8)     : make_float2(0.f, 0.f);
            float2 f2 = okr[s][0] ? load_pair_f(bp0, tig + k * 8 + 4) : make_float2(0.f, 0.f);
            float2 f3 = okr[s][1] ? load_pair_f(bp1, tig + k * 8 + 4) : make_float2(0.f, 0.f);
            if (apply) {
                float2 s0 = ((const float2*)smsc)[tig + k * 8];
                float2 h0 = ((const float2*)smsh)[tig + k * 8];
                float2 s1 = ((const float2*)smsc)[tig + k * 8 + 4];
                float2 h1 = ((const float2*)smsh)[tig + k * 8 + 4];
                f0.x = fmaxf(fmaf(f0.x, s0.x, h0.x), 0.f);
                f0.y = fmaxf(fmaf(f0.y, s0.y, h0.y), 0.f);
                f1.x = fmaxf(fmaf(f1.x, s0.x, h0.x), 0.f);
                f1.y = fmaxf(fmaf(f1.y, s0.y, h0.y), 0.f);
                f2.x = fmaxf(fmaf(f2.x, s1.x, h1.x), 0.f);
                f2.y = fmaxf(fmaf(f2.y, s1.y, h1.y), 0.f);
                f3.x = fmaxf(fmaf(f3.x, s1.x, h1.x), 0.f);
                f3.y = fmaxf(fmaf(f3.y, s1.y, h1.y), 0.f);
            }
            __half2 a0 = __floats2half2_rn(f0.x, f0.y);
            __half2 a1 = __floats2half2_rn(f1.x, f1.y);
            __half2 a2 = __floats2half2_rn(f2.x, f2.y);
            __half2 a3 = __floats2half2_rn(f3.x, f3.y);
            af[s][k][0] = *(uint32_t*)&a0;
            af[s][k][1] = *(uint32_t*)&a1;
            af[s][k][2] = *(uint32_t*)&a2;
            af[s][k][3] = *(uint32_t*)&a3;
        }
    }

    uint32_t b_base = ((lane & 7) + ((lane >> 4) << 3)) * 256 + (((lane >> 3) & 1) * 8) * 2;
    int col_t = tig * 2;

#pragma unroll 2
    for (int np = 0; np < 8; np++) {
        float e0[4] = {0,0,0,0}, o0[4] = {0,0,0,0};
        float e1[4] = {0,0,0,0}, o1[4] = {0,0,0,0};
#pragma unroll
        for (int k = 0; k < 8; k++) {
            uint32_t bh[4];
            uint32_t o = sw(b_base + np * 4096 + k * 32);
            ldm_x4(bh, sb + o);
            mma_f16(e0, af[0][k], bh[0], bh[1]);
            mma_f16(o0, af[0][k], bh[2], bh[3]);
            mma_f16(e1, af[1][k], bh[0], bh[1]);
            mma_f16(o1, af[1][k], bh[2], bh[3]);
        }
        int nb = np * 16;
#pragma unroll
        for (int s = 0; s < 2; s++) {
            float* ee = s ? e1 : e0; float* oo = s ? o1 : o0;
            int r0 = rb + s * 16 + groupID;
            int r1 = r0 + 8;
            if (okr[s][0]) {
                *(__half2*)(out + (size_t)r0 * D + nb + col_t)     = __floats2half2_rn(ee[0], ee[1]);
                *(__half2*)(out + (size_t)r0 * D + nb + 8 + col_t) = __floats2half2_rn(oo[0], oo[1]);
            }
            if (okr[s][1]) {
                *(__half2*)(out + (size_t)r1 * D + nb + col_t)     = __floats2half2_rn(ee[2], ee[3]);
                *(__half2*)(out + (size_t)r1 * D + nb + 8 + col_t) = __floats2half2_rn(oo[2], oo[3]);
            }
        }
    }
}

// ---------------- aggregation (gather, CSR, work-stealing) + bias + BN stats ----------------
__device__ __forceinline__ float4 h4_to_f4(uint2 raw) {
    __half2 a = *(__half2*)&raw.x;
    __half2 b = *(__half2*)&raw.y;
    float2 fa = __half22float2(a), fb = __half22float2(b);
    return make_float4(fa.x, fa.y, fb.x, fb.y);
}

__device__ __forceinline__ void acc4(float4& acc, float w, float4 v) {
    acc.x = fmaf(w, v.x, acc.x);
    acc.y = fmaf(w, v.y, acc.y);
    acc.z = fmaf(w, v.z, acc.z);
    acc.w = fmaf(w, v.w, acc.w);
}

__global__ __launch_bounds__(256) void k_agg(const __half* __restrict__ tmp,
                                             __half* __restrict__ outh,
                                             const float* __restrict__ bias,
                                             int layer) {
    __shared__ float bsum[D];
    __shared__ float bsq[D];
    int tid = threadIdx.x;
    if (tid < D) { bsum[tid] = 0.f; bsq[tid] = 0.f; }
    __syncthreads();

    int lane = tid & 31;
    const uint2* t2 = (const uint2*)tmp;
    float4 b4 = ((const float4*)bias)[lane];
    float ls0 = 0, ls1 = 0, ls2 = 0, ls3 = 0;
    float lq0 = 0, lq1 = 0, lq2 = 0, lq3 = 0;

    for (;;) {
        int base;
        if (lane == 0) base = atomicAdd(&g_ticket[layer], 4);
        base = __shfl_sync(0xffffffffu, base, 0);
        if (base >= NN) break;
        int rend = base + 4 < NN ? base + 4 : NN;
        for (int row = base; row < rend; row++) {
            float4 acc = make_float4(0.f, 0.f, 0.f, 0.f);
            int e0 = g_off[row], e1 = g_off[row + 1];
            int e = e0;
            for (; e + 4 <= e1; e += 4) {
                int2 p0 = __ldg(&g_edge[e]);
                int2 p1 = __ldg(&g_edge[e + 1]);
                int2 p2 = __ldg(&g_edge[e + 2]);
                int2 p3 = __ldg(&g_edge[e + 3]);
                float4 v0 = h4_to_f4(__ldg(&t2[p0.x * 32 + lane]));
                float4 v1 = h4_to_f4(__ldg(&t2[p1.x * 32 + lane]));
                float4 v2 = h4_to_f4(__ldg(&t2[p2.x * 32 + lane]));
                float4 v3 = h4_to_f4(__ldg(&t2[p3.x * 32 + lane]));
                acc4(acc, __int_as_float(p0.y), v0);
                acc4(acc, __int_as_float(p1.y), v1);
                acc4(acc, __int_as_float(p2.y), v2);
                acc4(acc, __int_as_float(p3.y), v3);
            }
            for (; e < e1; e++) {
                int2 pp = __ldg(&g_edge[e]);
                float4 v = h4_to_f4(__ldg(&t2[pp.x * 32 + lane]));
                acc4(acc, __int_as_float(pp.y), v);
            }
            float sw_ = g_selfw[row];
            float4 v = h4_to_f4(__ldg(&t2[row * 32 + lane]));
            acc.x = fmaf(sw_, v.x, acc.x) + b4.x;
            acc.y = fmaf(sw_, v.y, acc.y) + b4.y;
            acc.z = fmaf(sw_, v.z, acc.z) + b4.z;
            acc.w = fmaf(sw_, v.w, acc.w) + b4.w;
            uint2 packed;
            *(__half2*)&packed.x = __floats2half2_rn(acc.x, acc.y);
            *(__half2*)&packed.y = __floats2half2_rn(acc.z, acc.w);
            ((uint2*)outh)[row * 32 + lane] = packed;
            ls0 += acc.x; ls1 += acc.y; ls2 += acc.z; ls3 += acc.w;
            lq0 += acc.x * acc.x; lq1 += acc.y * acc.y;
            lq2 += acc.z * acc.z; lq3 += acc.w * acc.w;
        }
    }

    atomicAdd(&bsum[lane * 4 + 0], ls0); atomicAdd(&bsum[lane * 4 + 1], ls1);
    atomicAdd(&bsum[lane * 4 + 2], ls2); atomicAdd(&bsum[lane * 4 + 3], ls3);
    atomicAdd(&bsq[lane * 4 + 0], lq0);  atomicAdd(&bsq[lane * 4 + 1], lq1);
    atomicAdd(&bsq[lane * 4 + 2], lq2);  atomicAdd(&bsq[lane * 4 + 3], lq3);
    __syncthreads();
    if (tid < D) {
        int slot = (layer * NSLOT + (blockIdx.x & (NSLOT - 1))) * D + tid;
        atomicAdd(&g_psum3[slot], bsum[tid]);
        atomicAdd(&g_psq3[slot],  bsq[tid]);
    }
}

// ---------------- fused pool (BN affine layer 2) + MLP head ----------------
__global__ __launch_bounds__(256) void k_poolhead(const __half* __restrict__ h,
                                                  const float* __restrict__ gamma,
                                                  const float* __restrict__ beta,
                                                  const float* __restrict__ W1,
                                                  const float* __restrict__ b1,
                                                  const float* __restrict__ W2,
                                                  const float* __restrict__ b2,
                                                  float* __restrict__ out) {
    __shared__ float zs[D];
    __shared__ float partial[D];
    __shared__ float smsc[D];
    __shared__ float smsh[D];
    __shared__ float red[4];
    int g = blockIdx.x, t = threadIdx.x;
    int f = t & 127, hf = t >> 7;
    if (t < D) {
        float sc, sh;
        bn_affine(2, t, gamma, beta, sc, sh);
        smsc[t] = sc;
        smsh[t] = sh;
    }
    __syncthreads();
    int a = g_start[g], b = g_end[g];
    int n = b - a;
    int mid = a + (n >> 1);
    int lo = hf ? mid : a;
    int hi = hf ? b : mid;
    float sc = smsc[f], sh = smsh[f];
    float s0 = 0.f, s1 = 0.f;
    int i = lo;
    for (; i + 2 <= hi; i += 2) {
        s0 += fmaxf(fmaf(__half2float(h[(i + 0) * D + f]), sc, sh), 0.f);
        s1 += fmaxf(fmaf(__half2float(h[(i + 1) * D + f]), sc, sh), 0.f);
    }
    for (; i < hi; i++) s0 += fmaxf(fmaf(__half2float(h[i * D + f]), sc, sh), 0.f);
    float s = s0 + s1;
    if (hf) partial[f] = s;
    __syncthreads();
    if (!hf) zs[f] = (s + partial[f]) / (float)(n > 0 ? n : 1);
    __syncthreads();

    if (t < D) {
        float acc = b1[t];
#pragma unroll 8
        for (int k = 0; k < D; k++) acc = fmaf(zs[k], W1[k * D + t], acc);
        float hz = fmaxf(acc, 0.f);
        float p = hz * W2[t];
#pragma unroll
        for (int o = 16; o; o >>= 1) p += __shfl_down_sync(0xffffffffu, p, o);
        if ((t & 31) == 0) red[t >> 5] = p;
    }
    __syncthreads();
    if (t == 0) out[g] = red[0] + red[1] + red[2] + red[3] + b2[0];
}

// ---------------- launch ----------------
extern "C" void kernel_launch(void* const* d_in, const int* in_sizes, int n_in,
                              void* d_out, int out_size) {
    const float* x      = (const float*)d_in[0];
    const int*   ei     = (const int*)d_in[1];
    const int*   batch  = (const int*)d_in[2];
    const float* Ws     = (const float*)d_in[3];
    const float* bs     = (const float*)d_in[4];
    const float* gammas = (const float*)d_in[5];
    const float* betas  = (const float*)d_in[6];
    const float* W1     = (const float*)d_in[7];
    const float* b1     = (const float*)d_in[8];
    const float* W2     = (const float*)d_in[9];
    const float* b2     = (const float*)d_in[10];
    float* out = (float*)d_out;

    __half *A, *B, *wh;
    cudaGetSymbolAddress((void**)&A, g_bufA);
    cudaGetSymbolAddress((void**)&B, g_bufB);
    cudaGetSymbolAddress((void**)&wh, g_Wh16);
    cudaFuncSetAttribute(k_gemm16<float>,  cudaFuncAttributeMaxDynamicSharedMemorySize, MMASMEM);
    cudaFuncSetAttribute(k_gemm16<__half>, cudaFuncAttributeMaxDynamicSharedMemorySize, MMASMEM);

    static cudaStream_t s2 = [] {
        cudaStream_t s; cudaStreamCreateWithFlags(&s, cudaStreamNonBlocking); return s;
    }();
    static cudaEvent_t evFork = [] {
        cudaEvent_t e; cudaEventCreateWithFlags(&e, cudaEventDisableTiming); return e;
    }();
    static cudaEvent_t evJoin = [] {
        cudaEvent_t e; cudaEventCreateWithFlags(&e, cudaEventDisableTiming); return e;
    }();

    const int NB_E = (NE + 255) / 256;   // 3125

    cudaEventRecord(evFork, 0);
    cudaStreamWaitEvent(s2, evFork, 0);

    k_count<<<NB_E, 256, 0, s2>>>(ei);                                     // 0
    k_prepw<<<3 * D * D / 128, 128>>>(Ws);                                 // 1
    k_nodepart<<<SCAN_B, 256, 0, s2>>>();                                  // 2
    k_gemm16<float><<<NT2, 256, MMASMEM>>>(x, wh, B, 0, 0,
                                           gammas, betas);                 // 3 <- profiled
    k_scanpart<<<1, 512, 0, s2>>>();                                       // 4
    k_offsets<<<SCAN_B, 256, 0, s2>>>();                                   // 5
    k_fillbounds<<<NB_E, 256, 0, s2>>>(ei, batch);                         // 6

    cudaEventRecord(evJoin, s2);
    cudaStreamWaitEvent(0, evJoin, 0);

    for (int l = 0; l < 3; l++) {
        if (l > 0)
            k_gemm16<__half><<<NT2, 256, MMASMEM>>>(A, wh + l * D * D, B, 1, l - 1,
                                                    gammas + (l - 1) * D,
                                                    betas + (l - 1) * D);
        k_agg<<<AGG_GRID, 256>>>(B, A, bs + l * D, l);
    }

    k_poolhead<<<NG, 256>>>(A, gammas + 2 * D, betas + 2 * D, W1, b1, W2, b2, out);
}